// round 9
// baseline (speedup 1.0000x reference)
#include <cuda_runtime.h>
#include <cuda_bf16.h>
#include <cstdint>

#define S_LEN 512
#define BATCH 2048
#define DIN 64
#define HID 128

__device__ __forceinline__ float fast_tanh(float v) {
    float e = __expf(2.0f * v);
    return 1.0f - __fdividef(2.0f, e + 1.0f);
}
__device__ __forceinline__ void ldsm4(uint32_t r[4], uint32_t addr) {
    asm volatile("ldmatrix.sync.aligned.m8n8.x4.shared.b16 {%0,%1,%2,%3}, [%4];"
                 : "=r"(r[0]), "=r"(r[1]), "=r"(r[2]), "=r"(r[3]) : "r"(addr));
}
__device__ __forceinline__ void mma_bf16(float d[4], const uint32_t a[4],
                                         const uint32_t b0, const uint32_t b1) {
    asm volatile("mma.sync.aligned.m16n8k16.row.col.f32.bf16.bf16.f32 "
                 "{%0,%1,%2,%3}, {%4,%5,%6,%7}, {%8,%9}, {%0,%1,%2,%3};"
                 : "+f"(d[0]), "+f"(d[1]), "+f"(d[2]), "+f"(d[3])
                 : "r"(a[0]), "r"(a[1]), "r"(a[2]), "r"(a[3]), "r"(b0), "r"(b1));
}
__device__ __forceinline__ uint32_t smem_u32(const void* p) {
    uint32_t a;
    asm("{ .reg .u64 t; cvta.to.shared.u64 t, %1; cvt.u32.u64 %0, t; }"
        : "=r"(a) : "l"(p));
    return a;
}

// ======================= fused persistent RNN kernel ========================
// CTA = 16 batch rows, 8 warps; warp owns 16 output cols (2 n-tiles).
// Per step: GEMM2 P2 = a(t) @ W_hh^T + b_hh  AND  GEMM1 P1 = x(t+1) @ W_ih^T
// + b_ih run in one mma phase (independent chains). Both use 2-way bf16
// splits with 3 products. All B-fragments (W_hh, W_ih) preloaded to regs.

#define ROWB 272                    // W_hh / a row pitch (128 bf16 padded)
#define WSPL (HID * ROWB)           // 34816 per W_hh split plane
#define ASPL (16 * ROWB)            // 4352 per a split plane
#define ABUF (2 * ASPL)             // 8704 per a buffer
#define PROW 144                    // W_ih / x row pitch (64 bf16 padded)
#define IWSPL (HID * PROW)          // 18432 per W_ih split plane
#define XSPL (16 * PROW)            // 2304 per x split plane
#define XBUF (2 * XSPL)             // 4608 per x buffer

#define SM_W 0                      // W_hh splits: 69632
#define SM_A (2 * WSPL)             // a splits (2 buf): 17408
#define SM_X (SM_A + 2 * ABUF)      // overlay: W_ih init (36864) -> x bufs (9216)
#define L_SMEM (SM_X + 2 * IWSPL)   // 123904
#define L_THREADS 256

__global__ void __launch_bounds__(L_THREADS, 1)
rnn_fused_kernel(const float* __restrict__ x, const float* __restrict__ h0,
                 const float* __restrict__ Wih, const float* __restrict__ bih,
                 const float* __restrict__ Whh, const float* __restrict__ bhh,
                 float* __restrict__ out)
{
    extern __shared__ unsigned char smem[];
    const uint32_t smem_b = smem_u32(smem);

    const int tid  = threadIdx.x;
    const int warp = tid >> 5;
    const int lane = tid & 31;
    const int g    = lane >> 2;
    const int tq   = lane & 3;
    const int rowBase = blockIdx.x * 16;
    const int colW = warp * 16;

    // ---- stage W_hh splits (persistent) ----
    for (int idx = tid; idx < HID * HID; idx += L_THREADS) {
        const int n = idx >> 7, k = idx & 127;
        float w = Whh[idx];
        __nv_bfloat16 w0 = __float2bfloat16(w);
        __nv_bfloat16 w1 = __float2bfloat16(w - __bfloat162float(w0));
        const size_t off = (size_t)n * ROWB + (size_t)k * 2;
        *(__nv_bfloat16*)(smem + SM_W + off)        = w0;
        *(__nv_bfloat16*)(smem + SM_W + WSPL + off) = w1;
    }
    // ---- stage W_ih splits (transient, in overlay region) ----
    for (int idx = tid; idx < HID * DIN; idx += L_THREADS) {
        const int n = idx >> 6, k = idx & 63;
        float w = Wih[idx];
        __nv_bfloat16 w0 = __float2bfloat16(w);
        __nv_bfloat16 w1 = __float2bfloat16(w - __bfloat162float(w0));
        const size_t off = (size_t)n * PROW + (size_t)k * 2;
        *(__nv_bfloat16*)(smem + SM_X + off)         = w0;
        *(__nv_bfloat16*)(smem + SM_X + IWSPL + off) = w1;
    }
    __syncthreads();

    // ---- ldmatrix lane offsets ----
    const int q  = lane >> 3;
    const int lr = lane & 7;
    const uint32_t a_off  = (uint32_t)((lr + (q & 1) * 8) * ROWB + ((q & 2) ? 8 : 0) * 2);
    const uint32_t xa_off = (uint32_t)((lr + (q & 1) * 8) * PROW + ((q & 2) ? 8 : 0) * 2);
    const uint32_t bh_off = smem_b + SM_W +
        (uint32_t)((colW + lr + ((q & 2) ? 8 : 0)) * ROWB + ((q & 1) ? 8 : 0) * 2);
    const uint32_t bi_off = smem_b + SM_X +
        (uint32_t)((colW + lr + ((q & 2) ? 8 : 0)) * PROW + ((q & 1) ? 8 : 0) * 2);

    // ---- preload all B-fragments into registers ----
    uint32_t Bh0[8][4], Bh1[8][4];        // W_hh splits, k=128 -> 8 ks
    #pragma unroll
    for (int ks = 0; ks < 8; ++ks) {
        ldsm4(Bh0[ks], bh_off + ks * 32);
        ldsm4(Bh1[ks], bh_off + WSPL + ks * 32);
    }
    uint32_t Bi0[4][4], Bi1[4][4];        // W_ih splits, k=64 -> 4 ks
    #pragma unroll
    for (int ks = 0; ks < 4; ++ks) {
        ldsm4(Bi0[ks], bi_off + ks * 32);
        ldsm4(Bi1[ks], bi_off + IWSPL + ks * 32);
    }
    __syncthreads();   // overlay region now free for x buffers

    // ---- biases ----
    float bh0[2], bh1[2], bi0[2], bi1[2];
    #pragma unroll
    for (int nt = 0; nt < 2; ++nt) {
        bh0[nt] = bhh[colW + nt * 8 + tq * 2];
        bh1[nt] = bhh[colW + nt * 8 + tq * 2 + 1];
        bi0[nt] = bih[colW + nt * 8 + tq * 2];
        bi1[nt] = bih[colW + nt * 8 + tq * 2 + 1];
    }

    // ---- x staging map: thread -> (row sr, cols sc4..sc4+3) ----
    const int sr  = tid >> 4;
    const int sc4 = (tid & 15) * 4;
    const uint32_t xst = smem_b + SM_X + (uint32_t)(sr * PROW + sc4 * 2);

    // helper lambda-ish macro via code: stage a float4 into x split planes
    #define STAGE_X(bufidx, v)                                                  \
        do {                                                                    \
            __nv_bfloat16 h0a = __float2bfloat16((v).x);                        \
            __nv_bfloat16 h0b = __float2bfloat16((v).y);                        \
            __nv_bfloat16 h0c = __float2bfloat16((v).z);                        \
            __nv_bfloat16 h0d = __float2bfloat16((v).w);                        \
            __nv_bfloat16 r0a = __float2bfloat16((v).x - __bfloat162float(h0a));\
            __nv_bfloat16 r0b = __float2bfloat16((v).y - __bfloat162float(h0b));\
            __nv_bfloat16 r0c = __float2bfloat16((v).z - __bfloat162float(h0c));\
            __nv_bfloat16 r0d = __float2bfloat16((v).w - __bfloat162float(h0d));\
            uint2 p0, p1;                                                       \
            p0.x = (uint32_t)__bfloat16_as_ushort(h0a) |                        \
                   ((uint32_t)__bfloat16_as_ushort(h0b) << 16);                 \
            p0.y = (uint32_t)__bfloat16_as_ushort(h0c) |                        \
                   ((uint32_t)__bfloat16_as_ushort(h0d) << 16);                 \
            p1.x = (uint32_t)__bfloat16_as_ushort(r0a) |                        \
                   ((uint32_t)__bfloat16_as_ushort(r0b) << 16);                 \
            p1.y = (uint32_t)__bfloat16_as_ushort(r0c) |                        \
                   ((uint32_t)__bfloat16_as_ushort(r0d) << 16);                 \
            *(uint2*)(smem + SM_X + (bufidx) * XBUF + sr * PROW + sc4 * 2) = p0;\
            *(uint2*)(smem + SM_X + (bufidx) * XBUF + XSPL + sr * PROW + sc4 * 2) = p1;\
        } while (0)

    // ---- prologue: stage x(0) -> xbuf[1], x(1) -> xbuf[0] ----
    {
        float4 v0 = *(const float4*)&x[((size_t)0 * BATCH + rowBase + sr) * DIN + sc4];
        float4 v1 = *(const float4*)&x[((size_t)1 * BATCH + rowBase + sr) * DIN + sc4];
        STAGE_X(1, v0);
        STAGE_X(0, v1);
    }

    // ---- h registers ----
    float h[2][2][2], a[2][2][2];
    #pragma unroll
    for (int r = 0; r < 2; ++r) {
        const int row = rowBase + g + 8 * r;
        #pragma unroll
        for (int nt = 0; nt < 2; ++nt) {
            float2 hv = *(const float2*)&h0[(size_t)row * HID + colW + nt * 8 + tq * 2];
            h[r][nt][0] = hv.x; h[r][nt][1] = hv.y;
        }
    }
    __syncthreads();

    // ---- prologue GEMM1 on x(0) -> a(0) = U(0) * h0, stage into abuf[0] ----
    {
        float E0[2][4], E1[2][4], E2[2][4];
        #pragma unroll
        for (int nt = 0; nt < 2; ++nt) {
            E0[nt][0] = bi0[nt]; E0[nt][1] = bi1[nt];
            E0[nt][2] = bi0[nt]; E0[nt][3] = bi1[nt];
            #pragma unroll
            for (int e = 0; e < 4; ++e) { E1[nt][e] = 0.0f; E2[nt][e] = 0.0f; }
        }
        const uint32_t xb = smem_b + SM_X + 1 * XBUF + xa_off;
        #pragma unroll
        for (int ks = 0; ks < 4; ++ks) {
            uint32_t A0[4], A1[4];
            ldsm4(A0, xb + ks * 32);
            ldsm4(A1, xb + XSPL + ks * 32);
            #pragma unroll
            for (int nt = 0; nt < 2; ++nt) {
                mma_bf16(E0[nt], A0, Bi0[ks][2 * nt], Bi0[ks][2 * nt + 1]);
                mma_bf16(E1[nt], A0, Bi1[ks][2 * nt], Bi1[ks][2 * nt + 1]);
                mma_bf16(E2[nt], A1, Bi0[ks][2 * nt], Bi0[ks][2 * nt + 1]);
            }
        }
        #pragma unroll
        for (int r = 0; r < 2; ++r) {
            const int lrow = g + 8 * r;
            #pragma unroll
            for (int nt = 0; nt < 2; ++nt) {
                float U0 = E0[nt][2 * r] + E1[nt][2 * r] + E2[nt][2 * r];
                float U1 = E0[nt][2 * r + 1] + E1[nt][2 * r + 1] + E2[nt][2 * r + 1];
                float v0 = U0 * h[r][nt][0];
                float v1 = U1 * h[r][nt][1];
                a[r][nt][0] = v0; a[r][nt][1] = v1;
                __nv_bfloat16 s00 = __float2bfloat16(v0);
                __nv_bfloat16 s10 = __float2bfloat16(v1);
                __nv_bfloat16 s01 = __float2bfloat16(v0 - __bfloat162float(s00));
                __nv_bfloat16 s11 = __float2bfloat16(v1 - __bfloat162float(s10));
                const size_t o = (size_t)lrow * ROWB + (size_t)(colW + nt * 8 + tq * 2) * 2;
                *(__nv_bfloat162*)(smem + SM_A + o)        = __halves2bfloat162(s00, s10);
                *(__nv_bfloat162*)(smem + SM_A + ASPL + o) = __halves2bfloat162(s01, s11);
            }
        }
    }

    // ---- prefetch x(2) ----
    float4 xn = *(const float4*)&x[((size_t)2 * BATCH + rowBase + sr) * DIN + sc4];
    __syncthreads();

    const uint32_t abase = smem_b + SM_A;
    const uint32_t xbase = smem_b + SM_X;

    for (int t = 0; t < S_LEN; ++t) {
        const int buf = t & 1;

        // ==== mma phase: GEMM2 on a(t) + GEMM1 on x(t+1), 15 indep chains ====
        float D0[2][2][4], D1[2][2][4], D2[2][2][4];    // GEMM2 [parity][nt]
        float E0[2][4], E1[2][4], E2[2][4];             // GEMM1 [nt]
        #pragma unroll
        for (int nt = 0; nt < 2; ++nt) {
            D0[0][nt][0] = bh0[nt]; D0[0][nt][1] = bh1[nt];
            D0[0][nt][2] = bh0[nt]; D0[0][nt][3] = bh1[nt];
            E0[nt][0] = bi0[nt]; E0[nt][1] = bi1[nt];
            E0[nt][2] = bi0[nt]; E0[nt][3] = bi1[nt];
            #pragma unroll
            for (int e = 0; e < 4; ++e) {
                D0[1][nt][e] = 0.0f;
                D1[0][nt][e] = 0.0f; D1[1][nt][e] = 0.0f;
                D2[0][nt][e] = 0.0f; D2[1][nt][e] = 0.0f;
                E1[nt][e] = 0.0f; E2[nt][e] = 0.0f;
            }
        }

        const uint32_t abuf = abase + (uint32_t)buf * ABUF + a_off;
        const uint32_t xbuf = xbase + (uint32_t)buf * XBUF + xa_off;

        #pragma unroll
        for (int ks = 0; ks < 8; ++ks) {
            const int par = ks & 1;
            uint32_t A0[4], A1[4];
            ldsm4(A0, abuf + ks * 32);
            ldsm4(A1, abuf + ASPL + ks * 32);
            #pragma unroll
            for (int nt = 0; nt < 2; ++nt) {
                mma_bf16(D0[par][nt], A0, Bh0[ks][2 * nt], Bh0[ks][2 * nt + 1]);
                mma_bf16(D1[par][nt], A0, Bh1[ks][2 * nt], Bh1[ks][2 * nt + 1]);
                mma_bf16(D2[par][nt], A1, Bh0[ks][2 * nt], Bh0[ks][2 * nt + 1]);
            }
            if (ks < 4) {
                uint32_t X0[4], X1[4];
                ldsm4(X0, xbuf + ks * 32);
                ldsm4(X1, xbuf + XSPL + ks * 32);
                #pragma unroll
                for (int nt = 0; nt < 2; ++nt) {
                    mma_bf16(E0[nt], X0, Bi0[ks][2 * nt], Bi0[ks][2 * nt + 1]);
                    mma_bf16(E1[nt], X0, Bi1[ks][2 * nt], Bi1[ks][2 * nt + 1]);
                    mma_bf16(E2[nt], X1, Bi0[ks][2 * nt], Bi0[ks][2 * nt + 1]);
                }
            }
        }

        // ==== epilogue ====
        #pragma unroll
        for (int r = 0; r < 2; ++r) {
            const int lrow = g + 8 * r;
            #pragma unroll
            for (int nt = 0; nt < 2; ++nt) {
                float P0 = (D0[0][nt][2 * r]     + D0[1][nt][2 * r]) +
                           (D1[0][nt][2 * r]     + D1[1][nt][2 * r]) +
                           (D2[0][nt][2 * r]     + D2[1][nt][2 * r]);
                float P1 = (D0[0][nt][2 * r + 1] + D0[1][nt][2 * r + 1]) +
                           (D1[0][nt][2 * r + 1] + D1[1][nt][2 * r + 1]) +
                           (D2[0][nt][2 * r + 1] + D2[1][nt][2 * r + 1]);
                float h0n = fast_tanh(fmaf(P0, h[r][nt][0], a[r][nt][0]));
                float h1n = fast_tanh(fmaf(P1, h[r][nt][1], a[r][nt][1]));
                h[r][nt][0] = h0n; h[r][nt][1] = h1n;
                float U0 = E0[nt][2 * r]     + E1[nt][2 * r]     + E2[nt][2 * r];
                float U1 = E0[nt][2 * r + 1] + E1[nt][2 * r + 1] + E2[nt][2 * r + 1];
                float v0 = U0 * h0n;
                float v1 = U1 * h1n;
                a[r][nt][0] = v0; a[r][nt][1] = v1;

                __nv_bfloat16 s00 = __float2bfloat16(v0);
                __nv_bfloat16 s10 = __float2bfloat16(v1);
                __nv_bfloat16 s01 = __float2bfloat16(v0 - __bfloat162float(s00));
                __nv_bfloat16 s11 = __float2bfloat16(v1 - __bfloat162float(s10));
                const size_t o = (size_t)(buf ^ 1) * ABUF + (size_t)lrow * ROWB +
                                 (size_t)(colW + nt * 8 + tq * 2) * 2;
                *(__nv_bfloat162*)(smem + SM_A + o)        = __halves2bfloat162(s00, s10);
                *(__nv_bfloat162*)(smem + SM_A + ASPL + o) = __halves2bfloat162(s01, s11);
            }
        }

        // ---- stage x(t+2) splits into xbuf[buf^1]; prefetch x(t+3) ----
        STAGE_X(buf ^ 1, xn);
        {
            const int tn = (t + 3 < S_LEN) ? t + 3 : S_LEN - 1;
            xn = *(const float4*)&x[((size_t)tn * BATCH + rowBase + sr) * DIN + sc4];
        }
        __syncthreads();
    }

    // ---- write final hidden state ----
    #pragma unroll
    for (int r = 0; r < 2; ++r) {
        const int row = rowBase + g + 8 * r;
        #pragma unroll
        for (int nt = 0; nt < 2; ++nt)
            *(float2*)&out[(size_t)row * HID + colW + nt * 8 + tq * 2] =
                make_float2(h[r][nt][0], h[r][nt][1]);
    }
}

// ============================== launch =====================================

extern "C" void kernel_launch(void* const* d_in, const int* in_sizes, int n_in,
                              void* d_out, int out_size)
{
    const float* x   = (const float*)d_in[0];
    const float* h0  = (const float*)d_in[1];
    const float* Wih = (const float*)d_in[2];
    const float* bih = (const float*)d_in[3];
    const float* Whh = (const float*)d_in[4];
    const float* bhh = (const float*)d_in[5];

    cudaFuncSetAttribute(rnn_fused_kernel,
                         cudaFuncAttributeMaxDynamicSharedMemorySize, L_SMEM);
    rnn_fused_kernel<<<BATCH / 16, L_THREADS, L_SMEM>>>(
        x, h0, Wih, bih, Whh, bhh, (float*)d_out);
}

// round 10
// speedup vs baseline: 1.4276x; 1.4276x over previous
#include <cuda_runtime.h>
#include <cuda_bf16.h>
#include <cstdint>

#define S_LEN 512
#define BATCH 2048
#define DIN 64
#define HID 128
#define NROWS (S_LEN * BATCH)

// U scratch (split-packed bf16 pairs), FRAGMENT-MAJOR layout:
// per 16-row block bi: u32 index = bi*2048 + lwarp*256 + (r*2+nt)*64 + lane*2
__device__ uint32_t g_U[(size_t)NROWS * HID];

__device__ __forceinline__ float fast_tanh(float v) {
    float e = __expf(2.0f * v);
    return 1.0f - __fdividef(2.0f, e + 1.0f);
}
__device__ __forceinline__ void ldsm4(uint32_t r[4], uint32_t addr) {
    asm volatile("ldmatrix.sync.aligned.m8n8.x4.shared.b16 {%0,%1,%2,%3}, [%4];"
                 : "=r"(r[0]), "=r"(r[1]), "=r"(r[2]), "=r"(r[3]) : "r"(addr));
}
__device__ __forceinline__ void mma_bf16(float d[4], const uint32_t a[4],
                                         const uint32_t b0, const uint32_t b1) {
    asm volatile("mma.sync.aligned.m16n8k16.row.col.f32.bf16.bf16.f32 "
                 "{%0,%1,%2,%3}, {%4,%5,%6,%7}, {%8,%9}, {%0,%1,%2,%3};"
                 : "+f"(d[0]), "+f"(d[1]), "+f"(d[2]), "+f"(d[3])
                 : "r"(a[0]), "r"(a[1]), "r"(a[2]), "r"(a[3]), "r"(b0), "r"(b1));
}
__device__ __forceinline__ uint32_t smem_u32(const void* p) {
    uint32_t a;
    asm("{ .reg .u64 t; cvta.to.shared.u64 t, %1; cvt.u32.u64 %0, t; }"
        : "=r"(a) : "l"(p));
    return a;
}
// packed convert: low16 = bf16(lo), high16 = bf16(hi)
__device__ __forceinline__ uint32_t cvt2bf(float lo, float hi) {
    uint32_t r;
    asm("cvt.rn.bf16x2.f32 %0, %1, %2;" : "=r"(r) : "f"(hi), "f"(lo));
    return r;
}
// value of packed split element: low16 = main bf16, high16 = residual bf16
__device__ __forceinline__ float su(uint32_t p) {
    return __uint_as_float(p << 16) + __uint_as_float(p & 0xFFFF0000u);
}
// from pair (v0, v1): hi-plane word, lo-plane (residual) word
__device__ __forceinline__ void split_pair(float v0, float v1,
                                           uint32_t& hi, uint32_t& lo) {
    hi = cvt2bf(v0, v1);
    float f0 = __uint_as_float(hi << 16);
    float f1 = __uint_as_float(hi & 0xFFFF0000u);
    lo = cvt2bf(v0 - f0, v1 - f1);
}

// ============ Kernel 1: U = x @ W_ih^T + b_ih via bf16 mma ================

#define P2_THREADS 256
#define P2_GRID 592
#define NTILES (NROWS / 32)
#define PROW 144
#define PWSPL (HID * PROW)          // 18432 per W_ih split plane
#define PXSPL (32 * PROW)           // 4608 per x split plane
#define PXBUF (2 * PXSPL)           // 9216 per x buffer
#define PW 0
#define PX (2 * PWSPL)              // 36864
#define P2_SMEM (PX + 2 * PXBUF)    // 55296

__global__ void __launch_bounds__(P2_THREADS)
precompute_kernel(const float* __restrict__ x, const float* __restrict__ Wih,
                  const float* __restrict__ bih)
{
    extern __shared__ unsigned char sm[];
    const uint32_t smem_b = smem_u32(sm);

    const int tid  = threadIdx.x;
    const int warp = tid >> 5;
    const int lane = tid & 31;
    const int tq   = lane & 3;
    const int rg   = warp >> 2;
    const int colWp = (warp & 3) * 32;

    // ---- stage W_ih splits (once) ----
    for (int idx = tid; idx < HID * DIN; idx += P2_THREADS) {
        const int n = idx >> 6, k = idx & 63;
        float w = Wih[idx];
        __nv_bfloat16 w0 = __float2bfloat16(w);
        __nv_bfloat16 w1 = __float2bfloat16(w - __bfloat162float(w0));
        const size_t off = (size_t)n * PROW + (size_t)k * 2;
        *(__nv_bfloat16*)(sm + PW + off)         = w0;
        *(__nv_bfloat16*)(sm + PW + PWSPL + off) = w1;
    }

    float bi0[4], bi1[4];
    #pragma unroll
    for (int nt = 0; nt < 4; ++nt) {
        bi0[nt] = bih[colWp + nt * 8 + tq * 2];
        bi1[nt] = bih[colWp + nt * 8 + tq * 2 + 1];
    }

    const int q  = lane >> 3;
    const int lr = lane & 7;
    const uint32_t xa_lane = (uint32_t)((rg * 16 + lr + (q & 1) * 8) * PROW +
                                        ((q & 2) ? 8 : 0) * 2);
    const uint32_t wb = smem_b + PW +
        (uint32_t)((colWp + lr + ((q & 2) ? 8 : 0)) * PROW + ((q & 1) ? 8 : 0) * 2);

    const int sr = tid >> 3;
    const int sc = (tid & 7) * 8;

    // ---- prologue: load x for first tile ----
    int blk = blockIdx.x;
    float4 v0, v1;
    if (blk < NTILES) {
        const float* p = x + ((size_t)blk * 32 + sr) * DIN + sc;
        v0 = *(const float4*)p; v1 = *(const float4*)(p + 4);
    }
    int cur = 0;
    __syncthreads();

    while (blk < NTILES) {
        // ---- stage x tile splits: 2x STS.128 per thread ----
        {
            uint4 hi, lo;
            split_pair(v0.x, v0.y, hi.x, lo.x);
            split_pair(v0.z, v0.w, hi.y, lo.y);
            split_pair(v1.x, v1.y, hi.z, lo.z);
            split_pair(v1.z, v1.w, hi.w, lo.w);
            unsigned char* xb = sm + PX + cur * PXBUF + sr * PROW + sc * 2;
            *(uint4*)xb           = hi;
            *(uint4*)(xb + PXSPL) = lo;
        }
        __syncthreads();

        // ---- prefetch next tile ----
        const int nblk = blk + P2_GRID;
        if (nblk < NTILES) {
            const float* p = x + ((size_t)nblk * 32 + sr) * DIN + sc;
            v0 = *(const float4*)p; v1 = *(const float4*)(p + 4);
        }

        // ---- mma: 2-way splits, 3 products ----
        float D[4][4], Dc[4][4];
        #pragma unroll
        for (int nt = 0; nt < 4; ++nt) {
            D[nt][0] = bi0[nt]; D[nt][1] = bi1[nt];
            D[nt][2] = bi0[nt]; D[nt][3] = bi1[nt];
            Dc[nt][0] = Dc[nt][1] = Dc[nt][2] = Dc[nt][3] = 0.0f;
        }
        const uint32_t xa = smem_b + PX + (uint32_t)cur * PXBUF + xa_lane;
        #pragma unroll
        for (int ks = 0; ks < 4; ++ks) {
            uint32_t A0[4], A1[4];
            ldsm4(A0, xa + ks * 32);
            ldsm4(A1, xa + PXSPL + ks * 32);
            #pragma unroll
            for (int np = 0; np < 2; ++np) {
                uint32_t B0[4], B1[4];
                ldsm4(B0, wb + (uint32_t)(np * 16 * PROW) + ks * 32);
                ldsm4(B1, wb + PWSPL + (uint32_t)(np * 16 * PROW) + ks * 32);
                #pragma unroll
                for (int hf = 0; hf < 2; ++hf) {
                    const int nt = np * 2 + hf;
                    mma_bf16(D[nt],  A0, B0[2 * hf], B0[2 * hf + 1]);
                    mma_bf16(Dc[nt], A0, B1[2 * hf], B1[2 * hf + 1]);
                    mma_bf16(Dc[nt], A1, B0[2 * hf], B0[2 * hf + 1]);
                }
            }
        }

        // ---- write U, fragment-major coalesced ----
        const size_t biBlk = ((size_t)blk * 32 >> 4) + rg;
        #pragma unroll
        for (int r = 0; r < 2; ++r) {
            #pragma unroll
            for (int nt = 0; nt < 4; ++nt) {
                float s0 = D[nt][2 * r]     + Dc[nt][2 * r];
                float s1 = D[nt][2 * r + 1] + Dc[nt][2 * r + 1];
                uint32_t p, pr;
                split_pair(s0, s1, p, pr);
                uint2 o;
                o.x = __byte_perm(p, pr, 0x5410);   // elem0: main | resid
                o.y = __byte_perm(p, pr, 0x7632);   // elem1: main | resid
                const int lw  = 2 * (warp & 3) + (nt >> 1);
                const int ntl = nt & 1;
                *(uint2*)&g_U[biBlk * 2048 + lw * 256 + (r * 2 + ntl) * 64 +
                              lane * 2] = o;
            }
        }

        blk = nblk;
        cur ^= 1;
    }
}

// ============ Kernel 2: recurrence, 12 mma chains, 2-deep U prefetch =======

#define ROWB 272
#define WSPL (HID * ROWB)
#define ASPL (16 * ROWB)
#define ABUF (2 * ASPL)
#define SM_W 0
#define SM_A (2 * WSPL)
#define L_SMEM (SM_A + 2 * ABUF)
#define L_THREADS 256

__global__ void __launch_bounds__(L_THREADS, 1)
loop_kernel(const float* __restrict__ h0, const float* __restrict__ bhh,
            const float* __restrict__ Whh, float* __restrict__ out)
{
    extern __shared__ unsigned char smem[];
    const uint32_t smem_b = smem_u32(smem);

    const int tid  = threadIdx.x;
    const int warp = tid >> 5;
    const int lane = tid & 31;
    const int g    = lane >> 2;
    const int tq   = lane & 3;
    const int bx   = blockIdx.x;
    const int rowBase = bx * 16;
    const int colW = warp * 16;

    for (int idx = tid; idx < HID * HID; idx += L_THREADS) {
        const int n = idx >> 7, k = idx & 127;
        float w = Whh[idx];
        __nv_bfloat16 w0 = __float2bfloat16(w);
        __nv_bfloat16 w1 = __float2bfloat16(w - __bfloat162float(w0));
        const size_t off = (size_t)n * ROWB + (size_t)k * 2;
        *(__nv_bfloat16*)(smem + SM_W + off)        = w0;
        *(__nv_bfloat16*)(smem + SM_W + WSPL + off) = w1;
    }

    float bh0[2], bh1[2];
    #pragma unroll
    for (int nt = 0; nt < 2; ++nt) {
        bh0[nt] = bhh[colW + nt * 8 + tq * 2];
        bh1[nt] = bhh[colW + nt * 8 + tq * 2 + 1];
    }

    // U fragment address for (bi, r, nt): coalesced LDG.64
    #define U_IDX(bi, r, nt) ((size_t)(bi) * 2048 + warp * 256 + ((r) * 2 + (nt)) * 64 + lane * 2)

    // ---- h, a registers; stage a(0) splits ----
    float h[2][2][2], a[2][2][2];
    #pragma unroll
    for (int r = 0; r < 2; ++r) {
        const int row = rowBase + g + 8 * r;
        #pragma unroll
        for (int nt = 0; nt < 2; ++nt) {
            float2 hv = *(const float2*)&h0[(size_t)row * HID + colW + nt * 8 + tq * 2];
            h[r][nt][0] = hv.x; h[r][nt][1] = hv.y;
            uint2 uv = *(const uint2*)&g_U[U_IDX(bx, r, nt)];
            a[r][nt][0] = su(uv.x) * hv.x;
            a[r][nt][1] = su(uv.y) * hv.y;
        }
    }
    #pragma unroll
    for (int r = 0; r < 2; ++r) {
        const int lrow = g + 8 * r;
        #pragma unroll
        for (int nt = 0; nt < 2; ++nt) {
            uint32_t p, pr;
            split_pair(a[r][nt][0], a[r][nt][1], p, pr);
            const size_t o = (size_t)lrow * ROWB + (size_t)(colW + nt * 8 + tq * 2) * 2;
            *(uint32_t*)(smem + SM_A + o)        = p;
            *(uint32_t*)(smem + SM_A + ASPL + o) = pr;
        }
    }

    // ---- 2-deep U prefetch: Ua = U(1), Ub = U(2) ----
    uint2 Ua[2][2], Ub[2][2];
    #pragma unroll
    for (int r = 0; r < 2; ++r)
        #pragma unroll
        for (int nt = 0; nt < 2; ++nt) {
            Ua[r][nt] = *(const uint2*)&g_U[U_IDX(128 + bx, r, nt)];
            Ub[r][nt] = *(const uint2*)&g_U[U_IDX(256 + bx, r, nt)];
        }
    __syncthreads();

    const int q  = lane >> 3;
    const int lr = lane & 7;
    const uint32_t a_off = (uint32_t)((lr + (q & 1) * 8) * ROWB + ((q & 2) ? 8 : 0) * 2);
    const uint32_t b_off = smem_b + SM_W +
        (uint32_t)((colW + lr + ((q & 2) ? 8 : 0)) * ROWB + ((q & 1) ? 8 : 0) * 2);

    // ---- preload W_hh B-fragments (loop-invariant) ----
    uint32_t Bf0[8][4], Bf1[8][4];
    #pragma unroll
    for (int ks = 0; ks < 8; ++ks) {
        ldsm4(Bf0[ks], b_off + ks * 32);
        ldsm4(Bf1[ks], b_off + WSPL + ks * 32);
    }

    const uint32_t abase = smem_b + SM_A;

    for (int t = 0; t < S_LEN; ++t) {
        const int buf = t & 1;

        // ---- mma: 3 products x 2 ks-parities = 12 chains of depth 4 ----
        float D0[2][2][4], D1[2][2][4], D2[2][2][4];
        #pragma unroll
        for (int nt = 0; nt < 2; ++nt) {
            D0[0][nt][0] = bh0[nt]; D0[0][nt][1] = bh1[nt];
            D0[0][nt][2] = bh0[nt]; D0[0][nt][3] = bh1[nt];
            #pragma unroll
            for (int e = 0; e < 4; ++e) {
                D0[1][nt][e] = 0.0f;
                D1[0][nt][e] = 0.0f; D1[1][nt][e] = 0.0f;
                D2[0][nt][e] = 0.0f; D2[1][nt][e] = 0.0f;
            }
        }

        const uint32_t abuf = abase + (uint32_t)buf * ABUF + a_off;
        #pragma unroll
        for (int ks = 0; ks < 8; ++ks) {
            const int par = ks & 1;
            uint32_t A0[4], A1[4];
            ldsm4(A0, abuf + ks * 32);
            ldsm4(A1, abuf + ASPL + ks * 32);
            #pragma unroll
            for (int nt = 0; nt < 2; ++nt) {
                mma_bf16(D0[par][nt], A0, Bf0[ks][2 * nt], Bf0[ks][2 * nt + 1]);
                mma_bf16(D1[par][nt], A0, Bf1[ks][2 * nt], Bf1[ks][2 * nt + 1]);
                mma_bf16(D2[par][nt], A1, Bf0[ks][2 * nt], Bf0[ks][2 * nt + 1]);
            }
        }

        // ---- epilogue ----
        #pragma unroll
        for (int r = 0; r < 2; ++r) {
            const int lrow = g + 8 * r;
            #pragma unroll
            for (int nt = 0; nt < 2; ++nt) {
                float P0 = (D0[0][nt][2 * r]     + D0[1][nt][2 * r]) +
                           (D1[0][nt][2 * r]     + D1[1][nt][2 * r]) +
                           (D2[0][nt][2 * r]     + D2[1][nt][2 * r]);
                float P1 = (D0[0][nt][2 * r + 1] + D0[1][nt][2 * r + 1]) +
                           (D1[0][nt][2 * r + 1] + D1[1][nt][2 * r + 1]) +
                           (D2[0][nt][2 * r + 1] + D2[1][nt][2 * r + 1]);
                float h0n = fast_tanh(fmaf(P0, h[r][nt][0], a[r][nt][0]));
                float h1n = fast_tanh(fmaf(P1, h[r][nt][1], a[r][nt][1]));
                h[r][nt][0] = h0n; h[r][nt][1] = h1n;
                float v0 = su(Ua[r][nt].x) * h0n;
                float v1 = su(Ua[r][nt].y) * h1n;
                a[r][nt][0] = v0; a[r][nt][1] = v1;

                uint32_t p, pr;
                split_pair(v0, v1, p, pr);
                const size_t o = (size_t)(buf ^ 1) * ABUF + (size_t)lrow * ROWB +
                                 (size_t)(colW + nt * 8 + tq * 2) * 2;
                *(uint32_t*)(smem + SM_A + o)        = p;
                *(uint32_t*)(smem + SM_A + ASPL + o) = pr;
            }
        }

        // ---- shift prefetch: Ua <- Ub, issue Ub = U(t+3) ----
        {
            const int tn = (t + 3 < S_LEN) ? t + 3 : S_LEN - 1;
            const int bin = tn * 128 + bx;
            #pragma unroll
            for (int r = 0; r < 2; ++r)
                #pragma unroll
                for (int nt = 0; nt < 2; ++nt) {
                    Ua[r][nt] = Ub[r][nt];
                    Ub[r][nt] = *(const uint2*)&g_U[U_IDX(bin, r, nt)];
                }
        }
        __syncthreads();
    }

    #pragma unroll
    for (int r = 0; r < 2; ++r) {
        const int row = rowBase + g + 8 * r;
        #pragma unroll
        for (int nt = 0; nt < 2; ++nt)
            *(float2*)&out[(size_t)row * HID + colW + nt * 8 + tq * 2] =
                make_float2(h[r][nt][0], h[r][nt][1]);
    }
}

// ============================== launch =====================================

extern "C" void kernel_launch(void* const* d_in, const int* in_sizes, int n_in,
                              void* d_out, int out_size)
{
    const float* x   = (const float*)d_in[0];
    const float* h0  = (const float*)d_in[1];
    const float* Wih = (const float*)d_in[2];
    const float* bih = (const float*)d_in[3];
    const float* Whh = (const float*)d_in[4];
    const float* bhh = (const float*)d_in[5];

    cudaFuncSetAttribute(precompute_kernel,
                         cudaFuncAttributeMaxDynamicSharedMemorySize, P2_SMEM);
    precompute_kernel<<<P2_GRID, P2_THREADS, P2_SMEM>>>(x, Wih, bih);

    cudaFuncSetAttribute(loop_kernel,
                         cudaFuncAttributeMaxDynamicSharedMemorySize, L_SMEM);
    loop_kernel<<<BATCH / 16, L_THREADS, L_SMEM>>>(h0, bhh, Whh, (float*)d_out);
}